// round 2
// baseline (speedup 1.0000x reference)
#include <cuda_runtime.h>
#include <cuda_bf16.h>
#include <math.h>

// Problem constants (fixed by setup_inputs)
#define NN      50000
#define EE      800000
#define F_IN    128
#define WID     128
#define F_OUT   64

// ---------------- device scratch (no allocation allowed) ----------------
__device__ float g_h[NN * WID];             // hidden state ping buffer
__device__ float g_abc[NN * (3 * WID)];     // a|b|c concatenated per row
__device__ float g_Wcat[F_IN * 3 * WID];    // packed weights for current layer
__device__ float g_bcat[3 * WID];           // packed bias
__device__ float g_s[NN];                   // per-node sum of incoming edge weights
__device__ int   g_deg[NN];
__device__ int   g_rowptr[NN + 1];
__device__ int   g_cursor[NN];
__device__ int   g_src[EE];
__device__ float g_ew[EE];
__device__ int   g_is64;                    // edge_index dtype flag (1 = int64)

// Fetch edge index entry `idx` (flat index into the [2,E] array) honoring dtype flag.
__device__ __forceinline__ int edge_idx(const void* ei, int idx) {
    if (g_is64) return (int)((const long long*)ei)[idx];
    return ((const int*)ei)[idx];
}

// ---------------- dtype detection ----------------
// int64 little-endian values < 2^31: odd 32-bit words are all zero.
// Random int32 node ids in [0,50000): 64 consecutive zeros is impossible in practice.
__global__ void detect_kernel(const int* __restrict__ ei_raw) {
    if (threadIdx.x == 0) {
        int is64 = 1;
        #pragma unroll 4
        for (int i = 0; i < 64; i++) {
            if (ei_raw[2 * i + 1] != 0) { is64 = 0; break; }
        }
        g_is64 = is64;
    }
}

// ---------------- preprocessing ----------------
__global__ void zero_kernel() {
    int i = blockIdx.x * blockDim.x + threadIdx.x;
    if (i < NN) { g_deg[i] = 0; g_s[i] = 0.f; }
}

__global__ void hist_kernel(const void* __restrict__ ei,
                            const float* __restrict__ ea) {
    int e = blockIdx.x * blockDim.x + threadIdx.x;
    if (e < EE) {
        int dst = edge_idx(ei, EE + e);
        if ((unsigned)dst >= NN) return;   // IMA insurance
        atomicAdd(&g_deg[dst], 1);
        atomicAdd(&g_s[dst], ea[e]);
    }
}

// single-block exclusive scan over g_deg -> g_rowptr / g_cursor
__global__ void scan_kernel() {
    __shared__ int buf[2][1024];
    __shared__ int carry_s;
    if (threadIdx.x == 0) carry_s = 0;
    __syncthreads();
    for (int base = 0; base < NN; base += 1024) {
        int i = base + threadIdx.x;
        int v = (i < NN) ? g_deg[i] : 0;
        int sel = 0;
        buf[0][threadIdx.x] = v;
        __syncthreads();
        for (int off = 1; off < 1024; off <<= 1) {
            int t = buf[sel][threadIdx.x];
            if (threadIdx.x >= off) t += buf[sel][threadIdx.x - off];
            buf[sel ^ 1][threadIdx.x] = t;
            sel ^= 1;
            __syncthreads();
        }
        int inc = buf[sel][threadIdx.x] + carry_s;   // inclusive + carry
        if (i < NN) { g_rowptr[i + 1] = inc; g_cursor[i] = inc - v; }
        __syncthreads();
        if (threadIdx.x == 1023) carry_s = inc;
        __syncthreads();
    }
    if (threadIdx.x == 0) g_rowptr[0] = 0;
}

__global__ void scatter_kernel(const void* __restrict__ ei,
                               const float* __restrict__ ea) {
    int e = blockIdx.x * blockDim.x + threadIdx.x;
    if (e < EE) {
        int src = edge_idx(ei, e);
        int dst = edge_idx(ei, EE + e);
        if ((unsigned)src >= NN || (unsigned)dst >= NN) return;  // IMA insurance
        int pos = atomicAdd(&g_cursor[dst], 1);
        g_src[pos] = src;
        g_ew[pos]  = ea[e];
    }
}

// ---------------- weight packing: Wcat[k][0:C]=W1, [C:2C]=W2, [2C:3C]=W3 ----------------
__global__ void pack_w_kernel(const float* __restrict__ W1, const float* __restrict__ b1,
                              const float* __restrict__ W2,
                              const float* __restrict__ W3, const float* __restrict__ b3,
                              int K, int C) {
    int i = blockIdx.x * blockDim.x + threadIdx.x;
    int total = K * C;
    if (i < total) {
        int k = i / C, c = i % C;
        g_Wcat[k * 3 * C + c]         = W1[i];
        g_Wcat[k * 3 * C + C + c]     = W2[i];
        g_Wcat[k * 3 * C + 2 * C + c] = W3[i];
    }
    if (i < C) {
        g_bcat[i]         = b1[i];
        g_bcat[C + i]     = 0.f;
        g_bcat[2 * C + i] = b3[i];
    }
}

// ---------------- SGEMM: C[M x Ncol] = A[M x K] @ g_Wcat[K x Ncol] + g_bcat ----------------
#define BM 64
#define BN 64
#define BK 16
#define TM 4
#define TN 4

__global__ __launch_bounds__(256) void sgemm_kernel(const float* __restrict__ A,
                                                    int M, int K, int Ncol,
                                                    float* __restrict__ C) {
    __shared__ __align__(16) float As[BK][BM];
    __shared__ __align__(16) float Bs[BK][BN];

    int block_row = blockIdx.x * BM;
    int block_col = blockIdx.y * BN;
    int tid = threadIdx.x;
    int tx = tid & 15;       // 0..15  -> cols
    int ty = tid >> 4;       // 0..15  -> rows

    float acc[TM][TN] = {};

    for (int k0 = 0; k0 < K; k0 += BK) {
        // load A tile (BM x BK) transposed into As[k][m]
        #pragma unroll
        for (int i = tid; i < BM * BK; i += 256) {
            int m = i / BK, k = i % BK;
            int gm = block_row + m;
            As[k][m] = (gm < M) ? A[(size_t)gm * K + k0 + k] : 0.f;
        }
        // load B tile (BK x BN)
        #pragma unroll
        for (int i = tid; i < BK * BN; i += 256) {
            int k = i / BN, n = i % BN;
            Bs[k][n] = g_Wcat[(size_t)(k0 + k) * Ncol + block_col + n];
        }
        __syncthreads();

        #pragma unroll
        for (int k = 0; k < BK; k++) {
            float4 a4 = *reinterpret_cast<const float4*>(&As[k][ty * TM]);
            float4 b4 = *reinterpret_cast<const float4*>(&Bs[k][tx * TN]);
            float a[TM] = {a4.x, a4.y, a4.z, a4.w};
            float b[TN] = {b4.x, b4.y, b4.z, b4.w};
            #pragma unroll
            for (int i = 0; i < TM; i++)
                #pragma unroll
                for (int j = 0; j < TN; j++)
                    acc[i][j] += a[i] * b[j];
        }
        __syncthreads();
    }

    #pragma unroll
    for (int i = 0; i < TM; i++) {
        int gm = block_row + ty * TM + i;
        if (gm >= M) continue;
        int gn = block_col + tx * TN;
        float4 bias = *reinterpret_cast<const float4*>(&g_bcat[gn]);
        float4 v;
        v.x = acc[i][0] + bias.x;
        v.y = acc[i][1] + bias.y;
        v.z = acc[i][2] + bias.z;
        v.w = acc[i][3] + bias.w;
        *reinterpret_cast<float4*>(&C[(size_t)gm * Ncol + gn]) = v;
    }
}

// ---------------- SpMM + epilogue, F=128 (one warp per node, float4 per lane) ----------------
// abc row layout: [a(0:F) | b(F:2F) | c(2F:3F)], stride = 3F floats
// out[i] = act( sum_e w_e * a[src_e] - b[i]*s[i] + c[i] )
__global__ __launch_bounds__(256) void spmm128_kernel(const float* __restrict__ abc,
                                                      float* __restrict__ out,
                                                      int act /*0 lrelu, 1 lrelu+sigmoid*/) {
    const int F = 128;
    const int stride = 3 * F;
    int w = blockIdx.x * 8 + (threadIdx.x >> 5);
    if (w >= NN) return;
    int lane = threadIdx.x & 31;
    int fbase = lane * 4;

    float4 acc = make_float4(0.f, 0.f, 0.f, 0.f);
    int beg = g_rowptr[w], end = g_rowptr[w + 1];
    for (int e = beg; e < end; e++) {
        int   src = g_src[e];
        float wgt = g_ew[e];
        float4 av = *reinterpret_cast<const float4*>(abc + (size_t)src * stride + fbase);
        acc.x += wgt * av.x;
        acc.y += wgt * av.y;
        acc.z += wgt * av.z;
        acc.w += wgt * av.w;
    }
    float sv = g_s[w];
    float4 bv = *reinterpret_cast<const float4*>(abc + (size_t)w * stride + F + fbase);
    float4 cv = *reinterpret_cast<const float4*>(abc + (size_t)w * stride + 2 * F + fbase);
    float v[4];
    v[0] = acc.x - bv.x * sv + cv.x;
    v[1] = acc.y - bv.y * sv + cv.y;
    v[2] = acc.z - bv.z * sv + cv.z;
    v[3] = acc.w - bv.w * sv + cv.w;
    #pragma unroll
    for (int i = 0; i < 4; i++) {
        float t = v[i] > 0.f ? v[i] : 0.1f * v[i];
        if (act == 1) t = 1.f / (1.f + expf(-t));
        v[i] = t;
    }
    *reinterpret_cast<float4*>(out + (size_t)w * F + fbase) =
        make_float4(v[0], v[1], v[2], v[3]);
}

// ---------------- SpMM + epilogue, F=64 (one warp per node, float2 per lane) ----------------
__global__ __launch_bounds__(256) void spmm64_kernel(const float* __restrict__ abc,
                                                     float* __restrict__ out,
                                                     int act) {
    const int F = 64;
    const int stride = 3 * F;
    int w = blockIdx.x * 8 + (threadIdx.x >> 5);
    if (w >= NN) return;
    int lane = threadIdx.x & 31;
    int fbase = lane * 2;

    float2 acc = make_float2(0.f, 0.f);
    int beg = g_rowptr[w], end = g_rowptr[w + 1];
    for (int e = beg; e < end; e++) {
        int   src = g_src[e];
        float wgt = g_ew[e];
        float2 av = *reinterpret_cast<const float2*>(abc + (size_t)src * stride + fbase);
        acc.x += wgt * av.x;
        acc.y += wgt * av.y;
    }
    float sv = g_s[w];
    float2 bv = *reinterpret_cast<const float2*>(abc + (size_t)w * stride + F + fbase);
    float2 cv = *reinterpret_cast<const float2*>(abc + (size_t)w * stride + 2 * F + fbase);
    float v[2];
    v[0] = acc.x - bv.x * sv + cv.x;
    v[1] = acc.y - bv.y * sv + cv.y;
    #pragma unroll
    for (int i = 0; i < 2; i++) {
        float t = v[i] > 0.f ? v[i] : 0.1f * v[i];
        if (act == 1) t = 1.f / (1.f + expf(-t));
        v[i] = t;
    }
    *reinterpret_cast<float2*>(out + (size_t)w * F + fbase) = make_float2(v[0], v[1]);
}

// ---------------- host launch ----------------
extern "C" void kernel_launch(void* const* d_in, const int* in_sizes, int n_in,
                              void* d_out, int out_size) {
    const float* x  = (const float*)d_in[0];
    const void*  ei = d_in[1];                 // int32 or int64, detected on device
    const float* ea = (const float*)d_in[2];
    // d_in[3] = number_of_layers (fixed = 4)
    const float* W1_in  = (const float*)d_in[4];
    const float* b1_in  = (const float*)d_in[5];
    const float* W2_in  = (const float*)d_in[6];
    const float* W3_in  = (const float*)d_in[7];
    const float* b3_in  = (const float*)d_in[8];
    const float* W1_mid = (const float*)d_in[9];
    const float* b1_mid = (const float*)d_in[10];
    const float* W2_mid = (const float*)d_in[11];
    const float* W3_mid = (const float*)d_in[12];
    const float* b3_mid = (const float*)d_in[13];
    const float* W1_out = (const float*)d_in[14];
    const float* b1_out = (const float*)d_in[15];
    const float* W2_out = (const float*)d_in[16];
    const float* W3_out = (const float*)d_in[17];
    const float* b3_out = (const float*)d_in[18];

    float* out = (float*)d_out;

    float* d_h;
    float* d_abc;
    cudaGetSymbolAddress((void**)&d_h, g_h);
    cudaGetSymbolAddress((void**)&d_abc, g_abc);

    // --- preprocessing: dtype sniff, s[i] and CSR (once per call, reused for all layers) ---
    detect_kernel<<<1, 32>>>((const int*)ei);
    zero_kernel<<<(NN + 255) / 256, 256>>>();
    hist_kernel<<<(EE + 255) / 256, 256>>>(ei, ea);
    scan_kernel<<<1, 1024>>>();
    scatter_kernel<<<(EE + 255) / 256, 256>>>(ei, ea);

    const int spmm_blocks = (NN + 7) / 8;

    // --- layer 0 (in): x -> g_h ---
    {
        int K = F_IN, C = WID, Ncol = 3 * C;
        pack_w_kernel<<<(K * C + 255) / 256, 256>>>(W1_in, b1_in, W2_in, W3_in, b3_in, K, C);
        dim3 grid((NN + BM - 1) / BM, Ncol / BN);
        sgemm_kernel<<<grid, 256>>>(x, NN, K, Ncol, d_abc);
        spmm128_kernel<<<spmm_blocks, 256>>>(d_abc, d_h, 0);
    }

    // --- layers 1,2 (mid): g_h -> g_h ---
    for (int l = 0; l < 2; l++) {
        int K = WID, C = WID, Ncol = 3 * C;
        pack_w_kernel<<<(K * C + 255) / 256, 256>>>(W1_mid, b1_mid, W2_mid, W3_mid, b3_mid, K, C);
        dim3 grid((NN + BM - 1) / BM, Ncol / BN);
        sgemm_kernel<<<grid, 256>>>(d_h, NN, K, Ncol, d_abc);
        spmm128_kernel<<<spmm_blocks, 256>>>(d_abc, d_h, 0);
    }

    // --- layer 3 (out): g_h -> d_out (lrelu then sigmoid) ---
    {
        int K = WID, C = F_OUT, Ncol = 3 * C;
        pack_w_kernel<<<(K * C + 255) / 256, 256>>>(W1_out, b1_out, W2_out, W3_out, b3_out, K, C);
        dim3 grid((NN + BM - 1) / BM, Ncol / BN);
        sgemm_kernel<<<grid, 256>>>(d_h, NN, K, Ncol, d_abc);
        spmm64_kernel<<<spmm_blocks, 256>>>(d_abc, out, 1);
    }
}

// round 3
// speedup vs baseline: 1.3756x; 1.3756x over previous
#include <cuda_runtime.h>
#include <cuda_bf16.h>
#include <math.h>

// Problem constants (fixed by setup_inputs)
#define NN      50000
#define EE      800000
#define F_IN    128
#define WID     128
#define F_OUT   64

#define SCAN_B  1024
#define SCAN_NB ((NN + SCAN_B - 1) / SCAN_B)   // 49

// ---------------- device scratch (no allocation allowed) ----------------
__device__ float g_h[NN * WID];               // hidden state ping buffer
__device__ float g_abc[NN * (3 * WID)];       // a|b|c concatenated per row
__device__ float g_Wcat0[F_IN * 3 * WID];     // packed weights: in layer
__device__ float g_Wcat1[WID * 3 * WID];      // packed weights: mid layer
__device__ float g_Wcat2[WID * 3 * F_OUT];    // packed weights: out layer
__device__ float g_bcat0[3 * WID];
__device__ float g_bcat1[3 * WID];
__device__ float g_bcat2[3 * F_OUT];
__device__ float g_s[NN];                     // per-node sum of incoming edge weights
__device__ int   g_deg[NN];
__device__ int   g_rowptr[NN + 1];
__device__ int   g_cursor[NN];
__device__ int   g_bsum[SCAN_NB];
__device__ int   g_boff[SCAN_NB];
__device__ int   g_src[EE];
__device__ float g_ew[EE];
__device__ int   g_is64;                      // edge_index dtype flag (1 = int64)

__device__ __forceinline__ int edge_idx(const void* ei, int idx) {
    if (g_is64) return (int)((const long long*)ei)[idx];
    return ((const int*)ei)[idx];
}

// ---------------- dtype detection ----------------
__global__ void detect_kernel(const int* __restrict__ ei_raw) {
    if (threadIdx.x == 0) {
        int is64 = 1;
        for (int i = 0; i < 64; i++) {
            if (ei_raw[2 * i + 1] != 0) { is64 = 0; break; }
        }
        g_is64 = is64;
    }
}

// ---------------- preprocessing ----------------
__global__ void zero_kernel() {
    int i = blockIdx.x * blockDim.x + threadIdx.x;
    if (i < NN) { g_deg[i] = 0; g_s[i] = 0.f; }
}

__global__ void hist_kernel(const void* __restrict__ ei,
                            const float* __restrict__ ea) {
    int e = blockIdx.x * blockDim.x + threadIdx.x;
    if (e < EE) {
        int dst = edge_idx(ei, EE + e);
        if ((unsigned)dst >= NN) return;
        atomicAdd(&g_deg[dst], 1);
        atomicAdd(&g_s[dst], ea[e]);
    }
}

// --- parallel scan: per-block inclusive scan (warp shuffles) + block sums ---
__global__ __launch_bounds__(SCAN_B) void scan1_kernel() {
    __shared__ int wsum[32];
    int i = blockIdx.x * SCAN_B + threadIdx.x;
    int lane = threadIdx.x & 31;
    int wid  = threadIdx.x >> 5;
    int v = (i < NN) ? g_deg[i] : 0;
    int incl = v;
    #pragma unroll
    for (int off = 1; off < 32; off <<= 1) {
        int t = __shfl_up_sync(0xffffffffu, incl, off);
        if (lane >= off) incl += t;
    }
    if (lane == 31) wsum[wid] = incl;
    __syncthreads();
    if (wid == 0) {
        int s = (lane < 32) ? wsum[lane] : 0;
        #pragma unroll
        for (int off = 1; off < 32; off <<= 1) {
            int t = __shfl_up_sync(0xffffffffu, s, off);
            if (lane >= off) s += t;
        }
        wsum[lane] = s;
    }
    __syncthreads();
    if (wid > 0) incl += wsum[wid - 1];
    if (i < NN) g_rowptr[i + 1] = incl;        // partial (pre-carry)
    if (threadIdx.x == SCAN_B - 1) g_bsum[blockIdx.x] = incl;
}

__global__ void scan2_kernel() {
    if (threadIdx.x == 0) {
        int run = 0;
        for (int b = 0; b < SCAN_NB; b++) { g_boff[b] = run; run += g_bsum[b]; }
    }
}

__global__ __launch_bounds__(SCAN_B) void scan3_kernel() {
    int i = blockIdx.x * SCAN_B + threadIdx.x;
    if (i < NN) {
        int rp = g_rowptr[i + 1] + g_boff[blockIdx.x];
        g_rowptr[i + 1] = rp;
        g_cursor[i] = rp - g_deg[i];
    }
    if (i == 0) g_rowptr[0] = 0;
}

__global__ void scatter_kernel(const void* __restrict__ ei,
                               const float* __restrict__ ea) {
    int e = blockIdx.x * blockDim.x + threadIdx.x;
    if (e < EE) {
        int src = edge_idx(ei, e);
        int dst = edge_idx(ei, EE + e);
        if ((unsigned)src >= NN || (unsigned)dst >= NN) return;
        int pos = atomicAdd(&g_cursor[dst], 1);
        g_src[pos] = src;
        g_ew[pos]  = ea[e];
    }
}

// ---------------- weight packing: Wcat[k][0:C]=W1, [C:2C]=W2, [2C:3C]=W3 ----------------
__global__ void pack_w_kernel(const float* __restrict__ W1, const float* __restrict__ b1,
                              const float* __restrict__ W2,
                              const float* __restrict__ W3, const float* __restrict__ b3,
                              int K, int C, float* __restrict__ Wcat, float* __restrict__ bcat) {
    int i = blockIdx.x * blockDim.x + threadIdx.x;
    int total = K * C;
    if (i < total) {
        int k = i / C, c = i % C;
        Wcat[k * 3 * C + c]         = W1[i];
        Wcat[k * 3 * C + C + c]     = W2[i];
        Wcat[k * 3 * C + 2 * C + c] = W3[i];
    }
    if (i < C) {
        bcat[i]         = b1[i];
        bcat[C + i]     = 0.f;
        bcat[2 * C + i] = b3[i];
    }
}

// ---------------- SGEMM: C[M x Ncol] = A[M x K] @ W[K x Ncol] + bias ----------------
// 128x128 block tile, BK=16, 256 threads, 8x8 per thread (split 64+64 halves),
// double-buffered SMEM with register staging.
#define SB_M 128
#define SB_N 128
#define SB_K 16

__global__ __launch_bounds__(256) void sgemm_kernel(const float* __restrict__ A,
                                                    const float* __restrict__ W,
                                                    const float* __restrict__ bias,
                                                    int M, int K, int Ncol,
                                                    float* __restrict__ C) {
    __shared__ __align__(16) float As[2][SB_K][SB_M];
    __shared__ __align__(16) float Bs[2][SB_K][SB_N];

    const int tid = threadIdx.x;
    const int tx = tid & 15;        // 0..15 -> n
    const int ty = tid >> 4;        // 0..15 -> m
    const int row0 = blockIdx.x * SB_M;
    const int col0 = blockIdx.y * SB_N;

    // A tile: 128 rows x 16 k = 512 float4; f -> row=f>>2, kc=f&3
    const int fa0 = tid, fa1 = tid + 256;
    // B tile: 16 k-rows x 128 n = 512 float4; f -> kr=f>>5, nc=f&31
    const int fb0 = tid, fb1 = tid + 256;

    const int am0 = fa0 >> 2, akc0 = fa0 & 3;
    const int am1 = fa1 >> 2, akc1 = fa1 & 3;
    const int bkr0 = fb0 >> 5, bnc0 = fb0 & 31;
    const int bkr1 = fb1 >> 5, bnc1 = fb1 & 31;

    const bool aval0 = (row0 + am0) < M;
    const bool aval1 = (row0 + am1) < M;
    const bool bval0 = (col0 + bnc0 * 4) < Ncol;
    const bool bval1 = (col0 + bnc1 * 4) < Ncol;

    const float4 z4 = make_float4(0.f, 0.f, 0.f, 0.f);
    float4 ra0, ra1, rb0, rb1;

    // prologue: stage 0
    ra0 = aval0 ? *reinterpret_cast<const float4*>(A + (size_t)(row0 + am0) * K + akc0 * 4) : z4;
    ra1 = aval1 ? *reinterpret_cast<const float4*>(A + (size_t)(row0 + am1) * K + akc1 * 4) : z4;
    rb0 = bval0 ? *reinterpret_cast<const float4*>(W + (size_t)bkr0 * Ncol + col0 + bnc0 * 4) : z4;
    rb1 = bval1 ? *reinterpret_cast<const float4*>(W + (size_t)bkr1 * Ncol + col0 + bnc1 * 4) : z4;

    As[0][akc0 * 4 + 0][am0] = ra0.x; As[0][akc0 * 4 + 1][am0] = ra0.y;
    As[0][akc0 * 4 + 2][am0] = ra0.z; As[0][akc0 * 4 + 3][am0] = ra0.w;
    As[0][akc1 * 4 + 0][am1] = ra1.x; As[0][akc1 * 4 + 1][am1] = ra1.y;
    As[0][akc1 * 4 + 2][am1] = ra1.z; As[0][akc1 * 4 + 3][am1] = ra1.w;
    *reinterpret_cast<float4*>(&Bs[0][bkr0][bnc0 * 4]) = rb0;
    *reinterpret_cast<float4*>(&Bs[0][bkr1][bnc1 * 4]) = rb1;
    __syncthreads();

    float acc[8][8] = {};
    const int steps = K / SB_K;
    int cur = 0;

    for (int t = 0; t < steps; t++) {
        if (t + 1 < steps) {
            int k0 = (t + 1) * SB_K;
            ra0 = aval0 ? *reinterpret_cast<const float4*>(A + (size_t)(row0 + am0) * K + k0 + akc0 * 4) : z4;
            ra1 = aval1 ? *reinterpret_cast<const float4*>(A + (size_t)(row0 + am1) * K + k0 + akc1 * 4) : z4;
            rb0 = bval0 ? *reinterpret_cast<const float4*>(W + (size_t)(k0 + bkr0) * Ncol + col0 + bnc0 * 4) : z4;
            rb1 = bval1 ? *reinterpret_cast<const float4*>(W + (size_t)(k0 + bkr1) * Ncol + col0 + bnc1 * 4) : z4;
        }

        #pragma unroll
        for (int k = 0; k < SB_K; k++) {
            float4 a0 = *reinterpret_cast<const float4*>(&As[cur][k][ty * 4]);
            float4 a1 = *reinterpret_cast<const float4*>(&As[cur][k][64 + ty * 4]);
            float4 b0 = *reinterpret_cast<const float4*>(&Bs[cur][k][tx * 4]);
            float4 b1 = *reinterpret_cast<const float4*>(&Bs[cur][k][64 + tx * 4]);
            float av[8] = {a0.x, a0.y, a0.z, a0.w, a1.x, a1.y, a1.z, a1.w};
            float bv[8] = {b0.x, b0.y, b0.z, b0.w, b1.x, b1.y, b1.z, b1.w};
            #pragma unroll
            for (int i = 0; i < 8; i++)
                #pragma unroll
                for (int j = 0; j < 8; j++)
                    acc[i][j] += av[i] * bv[j];
        }

        if (t + 1 < steps) {
            int nxt = cur ^ 1;
            As[nxt][akc0 * 4 + 0][am0] = ra0.x; As[nxt][akc0 * 4 + 1][am0] = ra0.y;
            As[nxt][akc0 * 4 + 2][am0] = ra0.z; As[nxt][akc0 * 4 + 3][am0] = ra0.w;
            As[nxt][akc1 * 4 + 0][am1] = ra1.x; As[nxt][akc1 * 4 + 1][am1] = ra1.y;
            As[nxt][akc1 * 4 + 2][am1] = ra1.z; As[nxt][akc1 * 4 + 3][am1] = ra1.w;
            *reinterpret_cast<float4*>(&Bs[nxt][bkr0][bnc0 * 4]) = rb0;
            *reinterpret_cast<float4*>(&Bs[nxt][bkr1][bnc1 * 4]) = rb1;
        }
        __syncthreads();
        cur ^= 1;
    }

    // epilogue: rows {ty*4+i, 64+ty*4+i}, cols {tx*4.., 64+tx*4..}
    #pragma unroll
    for (int ii = 0; ii < 2; ii++) {
        #pragma unroll
        for (int i = 0; i < 4; i++) {
            int gm = row0 + ii * 64 + ty * 4 + i;
            if (gm >= M) continue;
            #pragma unroll
            for (int jj = 0; jj < 2; jj++) {
                int gn = col0 + jj * 64 + tx * 4;
                if (gn >= Ncol) continue;
                float4 bb = *reinterpret_cast<const float4*>(bias + gn);
                float4 v;
                v.x = acc[ii * 4 + i][jj * 4 + 0] + bb.x;
                v.y = acc[ii * 4 + i][jj * 4 + 1] + bb.y;
                v.z = acc[ii * 4 + i][jj * 4 + 2] + bb.z;
                v.w = acc[ii * 4 + i][jj * 4 + 3] + bb.w;
                *reinterpret_cast<float4*>(C + (size_t)gm * Ncol + gn) = v;
            }
        }
    }
}

// ---------------- SpMM + epilogue, F=128 (one warp per node, float4 per lane) ----------------
__global__ __launch_bounds__(256) void spmm128_kernel(const float* __restrict__ abc,
                                                      float* __restrict__ out,
                                                      int act) {
    const int F = 128;
    const int stride = 3 * F;
    int w = blockIdx.x * 8 + (threadIdx.x >> 5);
    if (w >= NN) return;
    int lane = threadIdx.x & 31;
    int fbase = lane * 4;

    float4 acc = make_float4(0.f, 0.f, 0.f, 0.f);
    int beg = g_rowptr[w], end = g_rowptr[w + 1];
    int e = beg;
    for (; e + 1 < end; e += 2) {
        int   s0 = g_src[e],     s1 = g_src[e + 1];
        float w0 = g_ew[e],      w1 = g_ew[e + 1];
        float4 a0 = *reinterpret_cast<const float4*>(abc + (size_t)s0 * stride + fbase);
        float4 a1 = *reinterpret_cast<const float4*>(abc + (size_t)s1 * stride + fbase);
        acc.x += w0 * a0.x + w1 * a1.x;
        acc.y += w0 * a0.y + w1 * a1.y;
        acc.z += w0 * a0.z + w1 * a1.z;
        acc.w += w0 * a0.w + w1 * a1.w;
    }
    if (e < end) {
        int   s0 = g_src[e];
        float w0 = g_ew[e];
        float4 a0 = *reinterpret_cast<const float4*>(abc + (size_t)s0 * stride + fbase);
        acc.x += w0 * a0.x; acc.y += w0 * a0.y; acc.z += w0 * a0.z; acc.w += w0 * a0.w;
    }
    float sv = g_s[w];
    float4 bv = *reinterpret_cast<const float4*>(abc + (size_t)w * stride + F + fbase);
    float4 cv = *reinterpret_cast<const float4*>(abc + (size_t)w * stride + 2 * F + fbase);
    float v[4];
    v[0] = acc.x - bv.x * sv + cv.x;
    v[1] = acc.y - bv.y * sv + cv.y;
    v[2] = acc.z - bv.z * sv + cv.z;
    v[3] = acc.w - bv.w * sv + cv.w;
    #pragma unroll
    for (int i = 0; i < 4; i++) {
        float t = v[i] > 0.f ? v[i] : 0.1f * v[i];
        if (act == 1) t = 1.f / (1.f + expf(-t));
        v[i] = t;
    }
    *reinterpret_cast<float4*>(out + (size_t)w * F + fbase) =
        make_float4(v[0], v[1], v[2], v[3]);
}

// ---------------- SpMM + epilogue, F=64 (one warp per node, float2 per lane) ----------------
__global__ __launch_bounds__(256) void spmm64_kernel(const float* __restrict__ abc,
                                                     float* __restrict__ out,
                                                     int act) {
    const int F = 64;
    const int stride = 3 * F;
    int w = blockIdx.x * 8 + (threadIdx.x >> 5);
    if (w >= NN) return;
    int lane = threadIdx.x & 31;
    int fbase = lane * 2;

    float2 acc = make_float2(0.f, 0.f);
    int beg = g_rowptr[w], end = g_rowptr[w + 1];
    int e = beg;
    for (; e + 1 < end; e += 2) {
        int   s0 = g_src[e],     s1 = g_src[e + 1];
        float w0 = g_ew[e],      w1 = g_ew[e + 1];
        float2 a0 = *reinterpret_cast<const float2*>(abc + (size_t)s0 * stride + fbase);
        float2 a1 = *reinterpret_cast<const float2*>(abc + (size_t)s1 * stride + fbase);
        acc.x += w0 * a0.x + w1 * a1.x;
        acc.y += w0 * a0.y + w1 * a1.y;
    }
    if (e < end) {
        int   s0 = g_src[e];
        float w0 = g_ew[e];
        float2 a0 = *reinterpret_cast<const float2*>(abc + (size_t)s0 * stride + fbase);
        acc.x += w0 * a0.x; acc.y += w0 * a0.y;
    }
    float sv = g_s[w];
    float2 bv = *reinterpret_cast<const float2*>(abc + (size_t)w * stride + F + fbase);
    float2 cv = *reinterpret_cast<const float2*>(abc + (size_t)w * stride + 2 * F + fbase);
    float v[2];
    v[0] = acc.x - bv.x * sv + cv.x;
    v[1] = acc.y - bv.y * sv + cv.y;
    #pragma unroll
    for (int i = 0; i < 2; i++) {
        float t = v[i] > 0.f ? v[i] : 0.1f * v[i];
        if (act == 1) t = 1.f / (1.f + expf(-t));
        v[i] = t;
    }
    *reinterpret_cast<float2*>(out + (size_t)w * F + fbase) = make_float2(v[0], v[1]);
}

// ---------------- host launch ----------------
extern "C" void kernel_launch(void* const* d_in, const int* in_sizes, int n_in,
                              void* d_out, int out_size) {
    const float* x  = (const float*)d_in[0];
    const void*  ei = d_in[1];                 // int32 or int64, detected on device
    const float* ea = (const float*)d_in[2];
    const float* W1_in  = (const float*)d_in[4];
    const float* b1_in  = (const float*)d_in[5];
    const float* W2_in  = (const float*)d_in[6];
    const float* W3_in  = (const float*)d_in[7];
    const float* b3_in  = (const float*)d_in[8];
    const float* W1_mid = (const float*)d_in[9];
    const float* b1_mid = (const float*)d_in[10];
    const float* W2_mid = (const float*)d_in[11];
    const float* W3_mid = (const float*)d_in[12];
    const float* b3_mid = (const float*)d_in[13];
    const float* W1_out = (const float*)d_in[14];
    const float* b1_out = (const float*)d_in[15];
    const float* W2_out = (const float*)d_in[16];
    const float* W3_out = (const float*)d_in[17];
    const float* b3_out = (const float*)d_in[18];

    float* out = (float*)d_out;

    float *d_h, *d_abc, *d_W0, *d_W1, *d_W2, *d_b0, *d_b1, *d_b2;
    cudaGetSymbolAddress((void**)&d_h,   g_h);
    cudaGetSymbolAddress((void**)&d_abc, g_abc);
    cudaGetSymbolAddress((void**)&d_W0,  g_Wcat0);
    cudaGetSymbolAddress((void**)&d_W1,  g_Wcat1);
    cudaGetSymbolAddress((void**)&d_W2,  g_Wcat2);
    cudaGetSymbolAddress((void**)&d_b0,  g_bcat0);
    cudaGetSymbolAddress((void**)&d_b1,  g_bcat1);
    cudaGetSymbolAddress((void**)&d_b2,  g_bcat2);

    // --- pack all weights up front (off the inter-layer critical path) ---
    pack_w_kernel<<<(F_IN * WID + 255) / 256, 256>>>(W1_in,  b1_in,  W2_in,  W3_in,  b3_in,  F_IN, WID,   d_W0, d_b0);
    pack_w_kernel<<<(WID * WID + 255) / 256, 256>>>(W1_mid, b1_mid, W2_mid, W3_mid, b3_mid, WID,  WID,   d_W1, d_b1);
    pack_w_kernel<<<(WID * F_OUT + 255) / 256, 256>>>(W1_out, b1_out, W2_out, W3_out, b3_out, WID, F_OUT, d_W2, d_b2);

    // --- preprocessing: dtype sniff, s[i] and CSR ---
    detect_kernel<<<1, 32>>>((const int*)ei);
    zero_kernel<<<(NN + 255) / 256, 256>>>();
    hist_kernel<<<(EE + 255) / 256, 256>>>(ei, ea);
    scan1_kernel<<<SCAN_NB, SCAN_B>>>();
    scan2_kernel<<<1, 32>>>();
    scan3_kernel<<<SCAN_NB, SCAN_B>>>();
    scatter_kernel<<<(EE + 255) / 256, 256>>>(ei, ea);

    const int spmm_blocks = (NN + 7) / 8;
    const int grid_m = (NN + SB_M - 1) / SB_M;

    // --- layer 0 (in): x -> g_h ---
    {
        int Ncol = 3 * WID;
        dim3 grid(grid_m, (Ncol + SB_N - 1) / SB_N);
        sgemm_kernel<<<grid, 256>>>(x, d_W0, d_b0, NN, F_IN, Ncol, d_abc);
        spmm128_kernel<<<spmm_blocks, 256>>>(d_abc, d_h, 0);
    }

    // --- layers 1,2 (mid): g_h -> g_h ---
    for (int l = 0; l < 2; l++) {
        int Ncol = 3 * WID;
        dim3 grid(grid_m, (Ncol + SB_N - 1) / SB_N);
        sgemm_kernel<<<grid, 256>>>(d_h, d_W1, d_b1, NN, WID, Ncol, d_abc);
        spmm128_kernel<<<spmm_blocks, 256>>>(d_abc, d_h, 0);
    }

    // --- layer 3 (out): g_h -> d_out (lrelu then sigmoid) ---
    {
        int Ncol = 3 * F_OUT;
        dim3 grid(grid_m, (Ncol + SB_N - 1) / SB_N);
        sgemm_kernel<<<grid, 256>>>(d_h, d_W2, d_b2, NN, WID, Ncol, d_abc);
        spmm64_kernel<<<spmm_blocks, 256>>>(d_abc, out, 1);
    }
}

// round 5
// speedup vs baseline: 1.7852x; 1.2978x over previous
#include <cuda_runtime.h>
#include <cuda_bf16.h>
#include <math.h>
#include <stdint.h>

// Problem constants (fixed by setup_inputs)
#define NN      50000
#define EE      800000
#define F_IN    128
#define WID     128
#define F_OUT   64
#define KK      128          // inner dim is 128 for every layer

#define SCAN_B  1024
#define SCAN_NB ((NN + SCAN_B - 1) / SCAN_B)   // 49

// ---------------- device scratch (no allocation allowed) ----------------
__device__ float g_h[NN * WID];               // hidden state ping buffer
__device__ float g_abc[NN * (3 * WID)];       // a|b|c concatenated per row
__device__ float g_Wcat0[F_IN * 3 * WID];     // packed weights: in layer
__device__ float g_Wcat1[WID * 3 * WID];      // packed weights: mid layer
__device__ float g_Wcat2[WID * 3 * F_OUT];    // packed weights: out layer
__device__ float g_bcat0[3 * WID];
__device__ float g_bcat1[3 * WID];
__device__ float g_bcat2[3 * F_OUT];
__device__ float g_s[NN];                     // per-node sum of incoming edge weights
__device__ int   g_deg[NN];
__device__ int   g_rowptr[NN + 1];
__device__ int   g_cursor[NN];
__device__ int   g_bsum[SCAN_NB];
__device__ int   g_boff[SCAN_NB];
__device__ int   g_src[EE];
__device__ float g_ew[EE];
__device__ int   g_is64;                      // edge_index dtype flag (1 = int64)

__device__ __forceinline__ int edge_idx(const void* ei, int idx) {
    if (g_is64) return (int)((const long long*)ei)[idx];
    return ((const int*)ei)[idx];
}

// ---------------- dtype detection (int64 LE < 2^31 -> odd words all zero) ----------------
__global__ void detect_kernel(const int* __restrict__ ei_raw) {
    __shared__ int nz;
    if (threadIdx.x == 0) nz = 0;
    __syncthreads();
    if (ei_raw[2 * threadIdx.x + 1] != 0) atomicAdd(&nz, 1);
    __syncthreads();
    if (threadIdx.x == 0) g_is64 = (nz == 0);
}

// ---------------- preprocessing ----------------
__global__ void zero_kernel() {
    int i = blockIdx.x * blockDim.x + threadIdx.x;
    if (i < NN) { g_deg[i] = 0; g_s[i] = 0.f; }
}

__global__ void hist_kernel(const void* __restrict__ ei,
                            const float* __restrict__ ea) {
    int e = blockIdx.x * blockDim.x + threadIdx.x;
    if (e < EE) {
        int dst = edge_idx(ei, EE + e);
        if ((unsigned)dst >= NN) return;
        atomicAdd(&g_deg[dst], 1);
        atomicAdd(&g_s[dst], ea[e]);
    }
}

// --- parallel scan: per-block inclusive scan (warp shuffles) + block sums ---
__global__ __launch_bounds__(SCAN_B) void scan1_kernel() {
    __shared__ int wsum[32];
    int i = blockIdx.x * SCAN_B + threadIdx.x;
    int lane = threadIdx.x & 31;
    int wid  = threadIdx.x >> 5;
    int v = (i < NN) ? g_deg[i] : 0;
    int incl = v;
    #pragma unroll
    for (int off = 1; off < 32; off <<= 1) {
        int t = __shfl_up_sync(0xffffffffu, incl, off);
        if (lane >= off) incl += t;
    }
    if (lane == 31) wsum[wid] = incl;
    __syncthreads();
    if (wid == 0) {
        int s = wsum[lane];
        #pragma unroll
        for (int off = 1; off < 32; off <<= 1) {
            int t = __shfl_up_sync(0xffffffffu, s, off);
            if (lane >= off) s += t;
        }
        wsum[lane] = s;
    }
    __syncthreads();
    if (wid > 0) incl += wsum[wid - 1];
    if (i < NN) g_rowptr[i + 1] = incl;        // partial (pre-carry)
    if (threadIdx.x == SCAN_B - 1) g_bsum[blockIdx.x] = incl;
}

__global__ void scan2_kernel() {
    if (threadIdx.x == 0) {
        int run = 0;
        for (int b = 0; b < SCAN_NB; b++) { g_boff[b] = run; run += g_bsum[b]; }
    }
}

__global__ __launch_bounds__(SCAN_B) void scan3_kernel() {
    int i = blockIdx.x * SCAN_B + threadIdx.x;
    if (i < NN) {
        int rp = g_rowptr[i + 1] + g_boff[blockIdx.x];
        g_rowptr[i + 1] = rp;
        g_cursor[i] = rp - g_deg[i];
    }
    if (i == 0) g_rowptr[0] = 0;
}

__global__ void scatter_kernel(const void* __restrict__ ei,
                               const float* __restrict__ ea) {
    int e = blockIdx.x * blockDim.x + threadIdx.x;
    if (e < EE) {
        int src = edge_idx(ei, e);
        int dst = edge_idx(ei, EE + e);
        if ((unsigned)src >= NN || (unsigned)dst >= NN) return;
        int pos = atomicAdd(&g_cursor[dst], 1);
        g_src[pos] = src;
        g_ew[pos]  = ea[e];
    }
}

// ---------------- weight packing: Wcat[k][0:C]=W1, [C:2C]=W2, [2C:3C]=W3 ----------------
__global__ void pack_w_kernel(const float* __restrict__ W1, const float* __restrict__ b1,
                              const float* __restrict__ W2,
                              const float* __restrict__ W3, const float* __restrict__ b3,
                              int K, int C, float* __restrict__ Wcat, float* __restrict__ bcat) {
    int i = blockIdx.x * blockDim.x + threadIdx.x;
    int total = K * C;
    if (i < total) {
        int k = i / C, c = i % C;
        Wcat[k * 3 * C + c]         = W1[i];
        Wcat[k * 3 * C + C + c]     = W2[i];
        Wcat[k * 3 * C + 2 * C + c] = W3[i];
    }
    if (i < C) {
        bcat[i]         = b1[i];
        bcat[C + i]     = 0.f;
        bcat[2 * C + i] = b3[i];
    }
}

// ================= tensor-core GEMM (3xTF32): C = A[M x 128] @ W[128 x Ncol] + bias =================
#define AS_S 36     // As padded stride (words): frag bank = 4g+t, conflict-free
#define BS_S 132    // Bs padded stride (words): same property
#define TG_SMEM ((2 * 128 * AS_S + 128 * BS_S) * 4)   // 104448 bytes

__device__ __forceinline__ uint32_t f2tf32(float x) {
    uint32_t r;
    asm("cvt.rna.tf32.f32 %0, %1;" : "=r"(r) : "f"(x));
    return r;
}

#define MMA_TF32(d, a0, a1, a2, a3, b0, b1)                                            \
    asm volatile("mma.sync.aligned.m16n8k8.row.col.f32.tf32.tf32.f32 "                  \
                 "{%0,%1,%2,%3},{%4,%5,%6,%7},{%8,%9},{%0,%1,%2,%3};"                   \
                 : "+f"(d[0]), "+f"(d[1]), "+f"(d[2]), "+f"(d[3])                       \
                 : "r"(a0), "r"(a1), "r"(a2), "r"(a3), "r"(b0), "r"(b1))

__global__ __launch_bounds__(256, 1) void tgemm_kernel(const float* __restrict__ A,
                                                       const float* __restrict__ W,
                                                       const float* __restrict__ bias,
                                                       int M, int Ncol,
                                                       float* __restrict__ C) {
    extern __shared__ float sm[];
    float* As = sm;                       // [2][128][AS_S]
    float* Bs = sm + 2 * 128 * AS_S;      // [128 n][BS_S] full-K transposed W tile

    const int tid = threadIdx.x;
    const int lane = tid & 31;
    const int g  = lane >> 2;     // 0..7
    const int tq = lane & 3;      // 0..3
    const int warp = tid >> 5;
    const int wm = warp & 1;      // 0..1  (m half)
    const int wn = warp >> 1;     // 0..3  (n quarter)
    const int row0 = blockIdx.x * 128;
    const int col0 = blockIdx.y * 128;

    const uint32_t as_base = (uint32_t)__cvta_generic_to_shared(As);

    // ---- cp.async loader for A stage s into buffer buf ----
    // OOB rows: bytes=0 (full zero-fill) AND pointer clamped to a valid row,
    // so no out-of-range address ever reaches the LSU.
    auto load_a = [&](int s, int buf) {
        int k0 = s * 32;
        #pragma unroll
        for (int p = 0; p < 4; p++) {
            int f = tid + p * 256;
            int row = f >> 3, c4 = f & 7;
            bool valid = (row0 + row) < M;
            size_t grow = valid ? (size_t)(row0 + row) : 0;
            const float* gp = A + grow * KK + k0 + c4 * 4;
            uint32_t sp = as_base + (uint32_t)((buf * 128 * AS_S + row * AS_S + c4 * 4) * 4);
            int bytes = valid ? 16 : 0;
            asm volatile("cp.async.ca.shared.global [%0], [%1], 16, %2;"
                         :: "r"(sp), "l"(gp), "r"(bytes));
        }
        asm volatile("cp.async.commit_group;");
    };

    // ---- prologue: A stages 0,1 in flight; fill Bs (transposed, full K) ----
    load_a(0, 0);
    load_a(1, 1);
    {
        int n = tid & 127;
        int kqb = tid >> 7;
        bool nval = (col0 + n) < Ncol;
        #pragma unroll
        for (int i2 = 0; i2 < 16; i2++) {
            int kr = (kqb + i2 * 2) * 4;
            float4 v = make_float4(0.f, 0.f, 0.f, 0.f);
            if (nval) {
                v.x = W[(size_t)(kr + 0) * Ncol + col0 + n];
                v.y = W[(size_t)(kr + 1) * Ncol + col0 + n];
                v.z = W[(size_t)(kr + 2) * Ncol + col0 + n];
                v.w = W[(size_t)(kr + 3) * Ncol + col0 + n];
            }
            *reinterpret_cast<float4*>(&Bs[n * BS_S + kr]) = v;
        }
    }
    asm volatile("cp.async.wait_group 1;");   // stage 0 complete
    __syncthreads();

    float acc[4][4][4];
    #pragma unroll
    for (int i = 0; i < 4; i++)
        #pragma unroll
        for (int j = 0; j < 4; j++)
            #pragma unroll
            for (int q = 0; q < 4; q++) acc[i][j][q] = 0.f;

    // ---- main loop: 4 stages of BK=32 (4 k8 steps each) ----
    #pragma unroll
    for (int t = 0; t < 4; t++) {
        const float* as = As + (t & 1) * (128 * AS_S);

        #pragma unroll
        for (int kk = 0; kk < 4; kk++) {
            const int ksl = kk * 8;            // k offset within stage
            const int ksg = t * 32 + ksl;      // global k offset (for Bs)

            uint32_t ahi[4][4], alo[4][4];
            #pragma unroll
            for (int i = 0; i < 4; i++) {
                int r0 = wm * 64 + i * 16 + g;
                float x0 = as[r0 * AS_S + ksl + tq];
                float x1 = as[(r0 + 8) * AS_S + ksl + tq];
                float x2 = as[r0 * AS_S + ksl + tq + 4];
                float x3 = as[(r0 + 8) * AS_S + ksl + tq + 4];
                ahi[i][0] = f2tf32(x0); alo[i][0] = __float_as_uint(x0 - __uint_as_float(ahi[i][0]));
                ahi[i][1] = f2tf32(x1); alo[i][1] = __float_as_uint(x1 - __uint_as_float(ahi[i][1]));
                ahi[i][2] = f2tf32(x2); alo[i][2] = __float_as_uint(x2 - __uint_as_float(ahi[i][2]));
                ahi[i][3] = f2tf32(x3); alo[i][3] = __float_as_uint(x3 - __uint_as_float(ahi[i][3]));
            }
            uint32_t bhi[4][2], blo[4][2];
            #pragma unroll
            for (int j = 0; j < 4; j++) {
                int nn = wn * 32 + j * 8 + g;
                float y0 = Bs[nn * BS_S + ksg + tq];
                float y1 = Bs[nn * BS_S + ksg + tq + 4];
                bhi[j][0] = f2tf32(y0); blo[j][0] = __float_as_uint(y0 - __uint_as_float(bhi[j][0]));
                bhi[j][1] = f2tf32(y1); blo[j][1] = __float_as_uint(y1 - __uint_as_float(bhi[j][1]));
            }
            #pragma unroll
            for (int i = 0; i < 4; i++)
                #pragma unroll
                for (int j = 0; j < 4; j++) {
                    MMA_TF32(acc[i][j], ahi[i][0], ahi[i][1], ahi[i][2], ahi[i][3], bhi[j][0], bhi[j][1]);
                    MMA_TF32(acc[i][j], ahi[i][0], ahi[i][1], ahi[i][2], ahi[i][3], blo[j][0], blo[j][1]);
                    MMA_TF32(acc[i][j], alo[i][0], alo[i][1], alo[i][2], alo[i][3], bhi[j][0], bhi[j][1]);
                }
        }

        if (t < 3) {
            __syncthreads();                       // done reading buffer (t&1)
            if (t + 2 < 4) load_a(t + 2, t & 1);   // refill freed buffer
            asm volatile("cp.async.wait_group %0;" :: "n"(1));  // next stage ready
            if (t == 2) asm volatile("cp.async.wait_group 0;"); // full drain before last stage
            __syncthreads();
        }
    }

    // ---- epilogue: bias + store (float2 per c-pair) ----
    #pragma unroll
    for (int i = 0; i < 4; i++) {
        int gm0 = row0 + wm * 64 + i * 16 + g;
        int gm1 = gm0 + 8;
        #pragma unroll
        for (int j = 0; j < 4; j++) {
            int gn = col0 + wn * 32 + j * 8 + 2 * tq;
            if (gn >= Ncol) continue;
            float2 bb = *reinterpret_cast<const float2*>(bias + gn);
            if (gm0 < M) {
                float2 v0 = make_float2(acc[i][j][0] + bb.x, acc[i][j][1] + bb.y);
                *reinterpret_cast<float2*>(C + (size_t)gm0 * Ncol + gn) = v0;
            }
            if (gm1 < M) {
                float2 v1 = make_float2(acc[i][j][2] + bb.x, acc[i][j][3] + bb.y);
                *reinterpret_cast<float2*>(C + (size_t)gm1 * Ncol + gn) = v1;
            }
        }
    }
}

// ---------------- SpMM + epilogue, F=128 (one warp per node, float4 per lane) ----------------
__global__ __launch_bounds__(256) void spmm128_kernel(const float* __restrict__ abc,
                                                      float* __restrict__ out,
                                                      int act) {
    const int F = 128;
    const int stride = 3 * F;
    int w = blockIdx.x * 8 + (threadIdx.x >> 5);
    if (w >= NN) return;
    int lane = threadIdx.x & 31;
    int fbase = lane * 4;

    float4 acc = make_float4(0.f, 0.f, 0.f, 0.f);
    int beg = g_rowptr[w], end = g_rowptr[w + 1];
    int e = beg;
    for (; e + 1 < end; e += 2) {
        int   s0 = g_src[e],     s1 = g_src[e + 1];
        float w0 = g_ew[e],      w1 = g_ew[e + 1];
        float4 a0 = *reinterpret_cast<const float4*>(abc + (size_t)s0 * stride + fbase);
        float4 a1 = *reinterpret_cast<const float4*>(abc + (size_t)s1 * stride + fbase);
        acc.x += w0 * a0.x + w1 * a1.x;
        acc.y += w0 * a0.y + w1 * a1.y;
        acc.z += w0 * a0.z + w1 * a1.z;
        acc.w += w0 * a0.w + w1 * a1.w;
    }
    if (e < end) {
        int   s0 = g_src[e];
        float w0 = g_ew[e];
        float4 a0 = *reinterpret_cast<const float4*>(abc + (size_t)s0 * stride + fbase);
        acc.x += w0 * a0.x; acc.y += w0 * a0.y; acc.z += w0 * a0.z; acc.w += w0 * a0.w;
    }
    float sv = g_s[w];
    float4 bv = *reinterpret_cast<const float4*>(abc + (size_t)w * stride + F + fbase);
    float4 cv = *reinterpret_cast<const float4*>(abc + (size_t)w * stride + 2 * F + fbase);
    float v[4];
    v[0] = acc.x - bv.x * sv + cv.x;
    v[1] = acc.y - bv.y * sv + cv.y;
    v[2] = acc.z - bv.z * sv + cv.z;
    v[3] = acc.w - bv.w * sv + cv.w;
    #pragma unroll
    for (int i = 0; i < 4; i++) {
        float t = v[i] > 0.f ? v[i] : 0.1f * v[i];
        if (act == 1) t = 1.f / (1.f + expf(-t));
        v[i] = t;
    }
    *reinterpret_cast<float4*>(out + (size_t)w * F + fbase) =
        make_float4(v[0], v[1], v[2], v[3]);
}

// ---------------- SpMM + epilogue, F=64 (one warp per node, float2 per lane) ----------------
__global__ __launch_bounds__(256) void spmm64_kernel(const float* __restrict__ abc,
                                                     float* __restrict__ out,
                                                     int act) {
    const int F = 64;
    const int stride = 3 * F;
    int w = blockIdx.x * 8 + (threadIdx.x >> 5);
    if (w >= NN) return;
    int lane = threadIdx.x & 31;
    int fbase = lane * 2;

    float2 acc = make_float2(0.f, 0.f);
    int beg = g_rowptr[w], end = g_rowptr[w + 1];
    int e = beg;
    for (; e + 1 < end; e += 2) {
        int   s0 = g_src[e],     s1 = g_src[e + 1];
        float w0 = g_ew[e],      w1 = g_ew[e + 1];
        float2 a0 = *reinterpret_cast<const float2*>(abc + (size_t)s0 * stride + fbase);
        float2 a1 = *reinterpret_cast<const float2*>(abc + (size_t)s1 * stride + fbase);
        acc.x += w0 * a0.x + w1 * a1.x;
        acc.y += w0 * a0.y + w1 * a1.y;
    }
    if (e < end) {
        int   s0 = g_src[e];
        float w0 = g_ew[e];
        float2 a0 = *reinterpret_cast<const float2*>(abc + (size_t)s0 * stride + fbase);
        acc.x += w0 * a0.x; acc.y += w0 * a0.y;
    }
    float sv = g_s[w];
    float2 bv = *reinterpret_cast<const float2*>(abc + (size_t)w * stride + F + fbase);
    float2 cv = *reinterpret_cast<const float2*>(abc + (size_t)w * stride + 2 * F + fbase);
    float v[2];
    v[0] = acc.x - bv.x * sv + cv.x;
    v[1] = acc.y - bv.y * sv + cv.y;
    #pragma unroll
    for (int i = 0; i < 2; i++) {
        float t = v[i] > 0.f ? v[i] : 0.1f * v[i];
        if (act == 1) t = 1.f / (1.f + expf(-t));
        v[i] = t;
    }
    *reinterpret_cast<float2*>(out + (size_t)w * F + fbase) = make_float2(v[0], v[1]);
}

// ---------------- host launch ----------------
extern "C" void kernel_launch(void* const* d_in, const int* in_sizes, int n_in,
                              void* d_out, int out_size) {
    const float* x  = (const float*)d_in[0];
    const void*  ei = d_in[1];                 // int32 or int64, detected on device
    const float* ea = (const float*)d_in[2];
    const float* W1_in  = (const float*)d_in[4];
    const float* b1_in  = (const float*)d_in[5];
    const float* W2_in  = (const float*)d_in[6];
    const float* W3_in  = (const float*)d_in[7];
    const float* b3_in  = (const float*)d_in[8];
    const float* W1_mid = (const float*)d_in[9];
    const float* b1_mid = (const float*)d_in[10];
    const float* W2_mid = (const float*)d_in[11];
    const float* W3_mid = (const float*)d_in[12];
    const float* b3_mid = (const float*)d_in[13];
    const float* W1_out = (const float*)d_in[14];
    const float* b1_out = (const float*)d_in[15];
    const float* W2_out = (const float*)d_in[16];
    const float* W3_out = (const float*)d_in[17];
    const float* b3_out = (const float*)d_in[18];

    float* out = (float*)d_out;

    float *d_h, *d_abc, *d_W0, *d_W1, *d_W2, *d_b0, *d_b1, *d_b2;
    cudaGetSymbolAddress((void**)&d_h,   g_h);
    cudaGetSymbolAddress((void**)&d_abc, g_abc);
    cudaGetSymbolAddress((void**)&d_W0,  g_Wcat0);
    cudaGetSymbolAddress((void**)&d_W1,  g_Wcat1);
    cudaGetSymbolAddress((void**)&d_W2,  g_Wcat2);
    cudaGetSymbolAddress((void**)&d_b0,  g_bcat0);
    cudaGetSymbolAddress((void**)&d_b1,  g_bcat1);
    cudaGetSymbolAddress((void**)&d_b2,  g_bcat2);

    cudaFuncSetAttribute(tgemm_kernel, cudaFuncAttributeMaxDynamicSharedMemorySize, TG_SMEM);

    // --- pack all weights up front ---
    pack_w_kernel<<<(F_IN * WID + 255) / 256, 256>>>(W1_in,  b1_in,  W2_in,  W3_in,  b3_in,  F_IN, WID,   d_W0, d_b0);
    pack_w_kernel<<<(WID * WID + 255) / 256, 256>>>(W1_mid, b1_mid, W2_mid, W3_mid, b3_mid, WID,  WID,   d_W1, d_b1);
    pack_w_kernel<<<(WID * F_OUT + 255) / 256, 256>>>(W1_out, b1_out, W2_out, W3_out, b3_out, WID, F_OUT, d_W2, d_b2);

    // --- preprocessing: dtype sniff, s[i] and CSR ---
    detect_kernel<<<1, 64>>>((const int*)ei);
    zero_kernel<<<(NN + 255) / 256, 256>>>();
    hist_kernel<<<(EE + 255) / 256, 256>>>(ei, ea);
    scan1_kernel<<<SCAN_NB, SCAN_B>>>();
    scan2_kernel<<<1, 32>>>();
    scan3_kernel<<<SCAN_NB, SCAN_B>>>();
    scatter_kernel<<<(EE + 255) / 256, 256>>>(ei, ea);

    const int spmm_blocks = (NN + 7) / 8;
    const int grid_m = (NN + 127) / 128;

    // --- layer 0 (in): x -> g_h ---
    {
        int Ncol = 3 * WID;
        dim3 grid(grid_m, (Ncol + 127) / 128);
        tgemm_kernel<<<grid, 256, TG_SMEM>>>(x, d_W0, d_b0, NN, Ncol, d_abc);
        spmm128_kernel<<<spmm_blocks, 256>>>(d_abc, d_h, 0);
    }

    // --- layers 1,2 (mid): g_h -> g_h ---
    for (int l = 0; l < 2; l++) {
        int Ncol = 3 * WID;
        dim3 grid(grid_m, (Ncol + 127) / 128);
        tgemm_kernel<<<grid, 256, TG_SMEM>>>(d_h, d_W1, d_b1, NN, Ncol, d_abc);
        spmm128_kernel<<<spmm_blocks, 256>>>(d_abc, d_h, 0);
    }

    // --- layer 3 (out): g_h -> d_out (lrelu then sigmoid) ---
    {
        int Ncol = 3 * F_OUT;
        dim3 grid(grid_m, (Ncol + 127) / 128);
        tgemm_kernel<<<grid, 256, TG_SMEM>>>(d_h, d_W2, d_b2, NN, Ncol, d_abc);
        spmm64_kernel<<<spmm_blocks, 256>>>(d_abc, out, 1);
    }
}

// round 6
// speedup vs baseline: 1.8284x; 1.0242x over previous
#include <cuda_runtime.h>
#include <cuda_bf16.h>
#include <math.h>
#include <stdint.h>

// Problem constants (fixed by setup_inputs)
#define NN      50000
#define EE      800000
#define F_IN    128
#define WID     128
#define F_OUT   64
#define KK      128          // inner dim is 128 for every layer

#define SCAN_B  1024
#define SCAN_NB ((NN + SCAN_B - 1) / SCAN_B)   // 49

// ---------------- device scratch (no allocation allowed) ----------------
__device__ float g_h[NN * WID];               // hidden state ping buffer
__device__ float g_abc[NN * (3 * WID)];       // GEMM output: a | d  (only 2*WID used now)
__device__ float g_Wcat0[F_IN * 3 * WID];     // packed weights: in layer
__device__ float g_Wcat1[WID * 3 * WID];      // packed weights: mid layer
__device__ float g_Wcat2[WID * 3 * F_OUT];    // packed weights: out layer
__device__ float g_bcat0[3 * WID];
__device__ float g_bcat1[3 * WID];
__device__ float g_bcat2[3 * F_OUT];
__device__ float g_s[NN];                     // per-node sum of incoming edge weights
__device__ int   g_deg[NN];
__device__ int   g_rowptr[NN + 1];
__device__ int   g_cursor[NN];
__device__ int   g_bsum[SCAN_NB];
__device__ int   g_boff[SCAN_NB];
__device__ int   g_src[EE];
__device__ float g_ew[EE];
__device__ int   g_is64;                      // edge_index dtype flag (1 = int64)

__device__ __forceinline__ int edge_idx(const void* ei, int idx) {
    if (g_is64) return (int)((const long long*)ei)[idx];
    return ((const int*)ei)[idx];
}

// ---------------- preprocessing ----------------
// zero + dtype detect fused (block 0's first 64 threads sniff int64 layout)
__global__ void zero_kernel(const int* __restrict__ ei_raw) {
    int i = blockIdx.x * blockDim.x + threadIdx.x;
    if (i < NN) { g_deg[i] = 0; g_s[i] = 0.f; }
    if (blockIdx.x == 0 && threadIdx.x == 0) {
        int is64 = 1;
        for (int t = 0; t < 64; t++)
            if (ei_raw[2 * t + 1] != 0) { is64 = 0; break; }
        g_is64 = is64;
    }
}

__global__ void hist_kernel(const void* __restrict__ ei,
                            const float* __restrict__ ea) {
    int e = blockIdx.x * blockDim.x + threadIdx.x;
    if (e < EE) {
        int dst = edge_idx(ei, EE + e);
        if ((unsigned)dst >= NN) return;
        atomicAdd(&g_deg[dst], 1);
        atomicAdd(&g_s[dst], ea[e]);
    }
}

// --- parallel scan: per-block inclusive scan (warp shuffles) + block sums ---
__global__ __launch_bounds__(SCAN_B) void scan1_kernel() {
    __shared__ int wsum[32];
    int i = blockIdx.x * SCAN_B + threadIdx.x;
    int lane = threadIdx.x & 31;
    int wid  = threadIdx.x >> 5;
    int v = (i < NN) ? g_deg[i] : 0;
    int incl = v;
    #pragma unroll
    for (int off = 1; off < 32; off <<= 1) {
        int t = __shfl_up_sync(0xffffffffu, incl, off);
        if (lane >= off) incl += t;
    }
    if (lane == 31) wsum[wid] = incl;
    __syncthreads();
    if (wid == 0) {
        int s = wsum[lane];
        #pragma unroll
        for (int off = 1; off < 32; off <<= 1) {
            int t = __shfl_up_sync(0xffffffffu, s, off);
            if (lane >= off) s += t;
        }
        wsum[lane] = s;
    }
    __syncthreads();
    if (wid > 0) incl += wsum[wid - 1];
    if (i < NN) g_rowptr[i + 1] = incl;        // partial (pre-carry)
    if (threadIdx.x == SCAN_B - 1) g_bsum[blockIdx.x] = incl;
}

__global__ void scan2_kernel() {
    if (threadIdx.x == 0) {
        int run = 0;
        for (int b = 0; b < SCAN_NB; b++) { g_boff[b] = run; run += g_bsum[b]; }
    }
}

__global__ __launch_bounds__(SCAN_B) void scan3_kernel() {
    int i = blockIdx.x * SCAN_B + threadIdx.x;
    if (i < NN) {
        int rp = g_rowptr[i + 1] + g_boff[blockIdx.x];
        g_rowptr[i + 1] = rp;
        g_cursor[i] = rp - g_deg[i];
    }
    if (i == 0) g_rowptr[0] = 0;
}

__global__ void scatter_kernel(const void* __restrict__ ei,
                               const float* __restrict__ ea) {
    int e = blockIdx.x * blockDim.x + threadIdx.x;
    if (e < EE) {
        int src = edge_idx(ei, e);
        int dst = edge_idx(ei, EE + e);
        if ((unsigned)src >= NN || (unsigned)dst >= NN) return;
        int pos = atomicAdd(&g_cursor[dst], 1);
        g_src[pos] = src;
        g_ew[pos]  = ea[e];
    }
}

// ---------------- weight packing: Wcat = [W1 | interleave(W2, W3)] ----------------
// Wcat[k][c]           = W1[k][c]            (c < C)
// Wcat[k][C + 2u]      = W2[k][u]
// Wcat[k][C + 2u + 1]  = W3[k][u]
// bcat:  [b1 | interleave(0, b3)]
__global__ void pack_w_kernel(const float* __restrict__ W1, const float* __restrict__ b1,
                              const float* __restrict__ W2,
                              const float* __restrict__ W3, const float* __restrict__ b3,
                              int K, int C, float* __restrict__ Wcat, float* __restrict__ bcat) {
    int i = blockIdx.x * blockDim.x + threadIdx.x;
    int total = K * C;
    if (i < total) {
        int k = i / C, c = i % C;
        Wcat[k * 3 * C + c]             = W1[i];
        Wcat[k * 3 * C + C + 2 * c]     = W2[i];
        Wcat[k * 3 * C + C + 2 * c + 1] = W3[i];
    }
    if (i < C) {
        bcat[i]             = b1[i];
        bcat[C + 2 * i]     = 0.f;
        bcat[C + 2 * i + 1] = b3[i];
    }
}

// ========== tensor-core GEMM (3xTF32) with fused LEConv epilogue ==========
// Computes Y = A[M x 128] @ Wcat[128 x 3*AC] + bcat, then writes per row:
//   out[row][c]        = Y[row][c] + b1[c]                      (c < AC: the "a" part)
//   out[row][AC + u]   = (Y[:,AC+2u+1] + b3[u]) - s[row]*Y[:,AC+2u]   (the "d" part)
// Out row stride = 2*AC.
#define AS_S 36     // As padded stride (words): frag bank = 4g+t, conflict-free
#define BS_S 132    // Bs padded stride (words): same property
#define TG_SMEM ((2 * 128 * AS_S + 128 * BS_S) * 4)   // 104448 bytes

__device__ __forceinline__ uint32_t f2tf32(float x) {
    uint32_t r;
    asm("cvt.rna.tf32.f32 %0, %1;" : "=r"(r) : "f"(x));
    return r;
}

#define MMA_TF32(d, a0, a1, a2, a3, b0, b1)                                            \
    asm volatile("mma.sync.aligned.m16n8k8.row.col.f32.tf32.tf32.f32 "                  \
                 "{%0,%1,%2,%3},{%4,%5,%6,%7},{%8,%9},{%0,%1,%2,%3};"                   \
                 : "+f"(d[0]), "+f"(d[1]), "+f"(d[2]), "+f"(d[3])                       \
                 : "r"(a0), "r"(a1), "r"(a2), "r"(a3), "r"(b0), "r"(b1))

__global__ __launch_bounds__(256, 1) void tgemm_kernel(const float* __restrict__ A,
                                                       const float* __restrict__ W,
                                                       const float* __restrict__ bias,
                                                       const float* __restrict__ svec,
                                                       int M, int AC,
                                                       float* __restrict__ out) {
    extern __shared__ float sm[];
    float* As = sm;                       // [2][128][AS_S]
    float* Bs = sm + 2 * 128 * AS_S;      // [128 n][BS_S] full-K transposed W tile

    const int Ncol = 3 * AC;
    const int OS   = 2 * AC;
    const int tid = threadIdx.x;
    const int lane = tid & 31;
    const int g  = lane >> 2;     // 0..7
    const int tq = lane & 3;      // 0..3
    const int warp = tid >> 5;
    const int wm = warp & 1;      // 0..1  (m half)
    const int wn = warp >> 1;     // 0..3  (n quarter)
    const int row0 = blockIdx.x * 128;
    const int col0 = blockIdx.y * 128;

    const uint32_t as_base = (uint32_t)__cvta_generic_to_shared(As);

    // ---- cp.async loader for A stage s into buffer buf (OOB rows clamped, bytes=0) ----
    auto load_a = [&](int s, int buf) {
        int k0 = s * 32;
        #pragma unroll
        for (int p = 0; p < 4; p++) {
            int f = tid + p * 256;
            int row = f >> 3, c4 = f & 7;
            bool valid = (row0 + row) < M;
            size_t grow = valid ? (size_t)(row0 + row) : 0;
            const float* gp = A + grow * KK + k0 + c4 * 4;
            uint32_t sp = as_base + (uint32_t)((buf * 128 * AS_S + row * AS_S + c4 * 4) * 4);
            int bytes = valid ? 16 : 0;
            asm volatile("cp.async.ca.shared.global [%0], [%1], 16, %2;"
                         :: "r"(sp), "l"(gp), "r"(bytes));
        }
        asm volatile("cp.async.commit_group;");
    };

    // ---- prologue: A stages 0,1 in flight; fill Bs (transposed, full K) ----
    load_a(0, 0);
    load_a(1, 1);
    {
        int n = tid & 127;
        int kqb = tid >> 7;
        bool nval = (col0 + n) < Ncol;
        #pragma unroll
        for (int i2 = 0; i2 < 16; i2++) {
            int kr = (kqb + i2 * 2) * 4;
            float4 v = make_float4(0.f, 0.f, 0.f, 0.f);
            if (nval) {
                v.x = W[(size_t)(kr + 0) * Ncol + col0 + n];
                v.y = W[(size_t)(kr + 1) * Ncol + col0 + n];
                v.z = W[(size_t)(kr + 2) * Ncol + col0 + n];
                v.w = W[(size_t)(kr + 3) * Ncol + col0 + n];
            }
            *reinterpret_cast<float4*>(&Bs[n * BS_S + kr]) = v;
        }
    }
    asm volatile("cp.async.wait_group 1;");   // stage 0 complete
    __syncthreads();

    float acc[4][4][4];
    #pragma unroll
    for (int i = 0; i < 4; i++)
        #pragma unroll
        for (int j = 0; j < 4; j++)
            #pragma unroll
            for (int q = 0; q < 4; q++) acc[i][j][q] = 0.f;

    // ---- main loop: 4 stages of BK=32 (4 k8 steps each) ----
    #pragma unroll
    for (int t = 0; t < 4; t++) {
        const float* as = As + (t & 1) * (128 * AS_S);

        #pragma unroll
        for (int kk = 0; kk < 4; kk++) {
            const int ksl = kk * 8;            // k offset within stage
            const int ksg = t * 32 + ksl;      // global k offset (for Bs)

            uint32_t ahi[4][4], alo[4][4];
            #pragma unroll
            for (int i = 0; i < 4; i++) {
                int r0 = wm * 64 + i * 16 + g;
                float x0 = as[r0 * AS_S + ksl + tq];
                float x1 = as[(r0 + 8) * AS_S + ksl + tq];
                float x2 = as[r0 * AS_S + ksl + tq + 4];
                float x3 = as[(r0 + 8) * AS_S + ksl + tq + 4];
                ahi[i][0] = f2tf32(x0); alo[i][0] = __float_as_uint(x0 - __uint_as_float(ahi[i][0]));
                ahi[i][1] = f2tf32(x1); alo[i][1] = __float_as_uint(x1 - __uint_as_float(ahi[i][1]));
                ahi[i][2] = f2tf32(x2); alo[i][2] = __float_as_uint(x2 - __uint_as_float(ahi[i][2]));
                ahi[i][3] = f2tf32(x3); alo[i][3] = __float_as_uint(x3 - __uint_as_float(ahi[i][3]));
            }
            uint32_t bhi[4][2], blo[4][2];
            #pragma unroll
            for (int j = 0; j < 4; j++) {
                int nn = wn * 32 + j * 8 + g;
                float y0 = Bs[nn * BS_S + ksg + tq];
                float y1 = Bs[nn * BS_S + ksg + tq + 4];
                bhi[j][0] = f2tf32(y0); blo[j][0] = __float_as_uint(y0 - __uint_as_float(bhi[j][0]));
                bhi[j][1] = f2tf32(y1); blo[j][1] = __float_as_uint(y1 - __uint_as_float(bhi[j][1]));
            }
            #pragma unroll
            for (int i = 0; i < 4; i++)
                #pragma unroll
                for (int j = 0; j < 4; j++) {
                    MMA_TF32(acc[i][j], ahi[i][0], ahi[i][1], ahi[i][2], ahi[i][3], bhi[j][0], bhi[j][1]);
                    MMA_TF32(acc[i][j], ahi[i][0], ahi[i][1], ahi[i][2], ahi[i][3], blo[j][0], blo[j][1]);
                    MMA_TF32(acc[i][j], alo[i][0], alo[i][1], alo[i][2], alo[i][3], bhi[j][0], bhi[j][1]);
                }
        }

        if (t < 3) {
            __syncthreads();                       // done reading buffer (t&1)
            if (t + 2 < 4) load_a(t + 2, t & 1);   // refill freed buffer
            asm volatile("cp.async.wait_group %0;" :: "n"(1));  // next stage ready
            if (t == 2) asm volatile("cp.async.wait_group 0;"); // full drain before last stage
            __syncthreads();
        }
    }

    // ---- fused epilogue ----
    // c-frag mapping: acc[i][j] = {row gm0 cols (gn, gn+1), row gm1 cols (gn, gn+1)}
    #pragma unroll
    for (int i = 0; i < 4; i++) {
        int gm0 = row0 + wm * 64 + i * 16 + g;
        int gm1 = gm0 + 8;
        float s0 = (gm0 < M) ? svec[gm0] : 0.f;
        float s1 = (gm1 < M) ? svec[gm1] : 0.f;
        #pragma unroll
        for (int j = 0; j < 4; j++) {
            int gn = col0 + wn * 32 + j * 8 + 2 * tq;
            if (gn >= Ncol) continue;
            if (gn < AC) {
                // "a" part: plain bias add, float2 store
                float2 bb = *reinterpret_cast<const float2*>(bias + gn);
                if (gm0 < M) {
                    float2 v0 = make_float2(acc[i][j][0] + bb.x, acc[i][j][1] + bb.y);
                    *reinterpret_cast<float2*>(out + (size_t)gm0 * OS + gn) = v0;
                }
                if (gm1 < M) {
                    float2 v1 = make_float2(acc[i][j][2] + bb.x, acc[i][j][3] + bb.y);
                    *reinterpret_cast<float2*>(out + (size_t)gm1 * OS + gn) = v1;
                }
            } else {
                // pair (b_u, c_u): d_u = (c_u + b3_u) - s*b_u
                int u = (gn - AC) >> 1;
                float b3v = bias[gn + 1];
                if (gm0 < M)
                    out[(size_t)gm0 * OS + AC + u] = (acc[i][j][1] + b3v) - s0 * acc[i][j][0];
                if (gm1 < M)
                    out[(size_t)gm1 * OS + AC + u] = (acc[i][j][3] + b3v) - s1 * acc[i][j][2];
            }
        }
    }
}

// ---------------- SpMM + epilogue, F=128 (one warp per node, float4 per lane) ----------------
// ad row layout: [a(0:F) | d(F:2F)], stride = 2F
// out[i] = act( sum_e w_e * a[src_e] + d[i] )
__global__ __launch_bounds__(256) void spmm128_kernel(const float* __restrict__ ad,
                                                      float* __restrict__ out,
                                                      int act) {
    const int F = 128;
    const int stride = 2 * F;
    int w = blockIdx.x * 8 + (threadIdx.x >> 5);
    if (w >= NN) return;
    int lane = threadIdx.x & 31;
    int fbase = lane * 4;

    float4 acc = make_float4(0.f, 0.f, 0.f, 0.f);
    int beg = g_rowptr[w], end = g_rowptr[w + 1];
    int e = beg;
    for (; e + 1 < end; e += 2) {
        int   s0 = g_src[e],     s1 = g_src[e + 1];
        float w0 = g_ew[e],      w1 = g_ew[e + 1];
        float4 a0 = *reinterpret_cast<const float4*>(ad + (size_t)s0 * stride + fbase);
        float4 a1 = *reinterpret_cast<const float4*>(ad + (size_t)s1 * stride + fbase);
        acc.x += w0 * a0.x + w1 * a1.x;
        acc.y += w0 * a0.y + w1 * a1.y;
        acc.z += w0 * a0.z + w1 * a1.z;
        acc.w += w0 * a0.w + w1 * a1.w;
    }
    if (e < end) {
        int   s0 = g_src[e];
        float w0 = g_ew[e];
        float4 a0 = *reinterpret_cast<const float4*>(ad + (size_t)s0 * stride + fbase);
        acc.x += w0 * a0.x; acc.y += w0 * a0.y; acc.z += w0 * a0.z; acc.w += w0 * a0.w;
    }
    float4 dv = *reinterpret_cast<const float4*>(ad + (size_t)w * stride + F + fbase);
    float v[4];
    v[0] = acc.x + dv.x;
    v[1] = acc.y + dv.y;
    v[2] = acc.z + dv.z;
    v[3] = acc.w + dv.w;
    #pragma unroll
    for (int i = 0; i < 4; i++) {
        float t = v[i] > 0.f ? v[i] : 0.1f * v[i];
        if (act == 1) t = 1.f / (1.f + expf(-t));
        v[i] = t;
    }
    *reinterpret_cast<float4*>(out + (size_t)w * F + fbase) =
        make_float4(v[0], v[1], v[2], v[3]);
}

// ---------------- SpMM + epilogue, F=64 (one warp per node, float2 per lane) ----------------
__global__ __launch_bounds__(256) void spmm64_kernel(const float* __restrict__ ad,
                                                     float* __restrict__ out,
                                                     int act) {
    const int F = 64;
    const int stride = 2 * F;
    int w = blockIdx.x * 8 + (threadIdx.x >> 5);
    if (w >= NN) return;
    int lane = threadIdx.x & 31;
    int fbase = lane * 2;

    float2 acc = make_float2(0.f, 0.f);
    int beg = g_rowptr[w], end = g_rowptr[w + 1];
    int e = beg;
    for (; e + 1 < end; e += 2) {
        int   s0 = g_src[e],     s1 = g_src[e + 1];
        float w0 = g_ew[e],      w1 = g_ew[e + 1];
        float2 a0 = *reinterpret_cast<const float2*>(ad + (size_t)s0 * stride + fbase);
        float2 a1 = *reinterpret_cast<const float2*>(ad + (size_t)s1 * stride + fbase);
        acc.x += w0 * a0.x + w1 * a1.x;
        acc.y += w0 * a0.y + w1 * a1.y;
    }
    if (e < end) {
        int   s0 = g_src[e];
        float w0 = g_ew[e];
        float2 a0 = *reinterpret_cast<const float2*>(ad + (size_t)s0 * stride + fbase);
        acc.x += w0 * a0.x; acc.y += w0 * a0.y;
    }
    float2 dv = *reinterpret_cast<const float2*>(ad + (size_t)w * stride + F + fbase);
    float v[2];
    v[0] = acc.x + dv.x;
    v[1] = acc.y + dv.y;
    #pragma unroll
    for (int i = 0; i < 2; i++) {
        float t = v[i] > 0.f ? v[i] : 0.1f * v[i];
        if (act == 1) t = 1.f / (1.f + expf(-t));
        v[i] = t;
    }
    *reinterpret_cast<float2*>(out + (size_t)w * F + fbase) = make_float2(v[0], v[1]);
}

// ---------------- host launch ----------------
extern "C" void kernel_launch(void* const* d_in, const int* in_sizes, int n_in,
                              void* d_out, int out_size) {
    const float* x  = (const float*)d_in[0];
    const void*  ei = d_in[1];                 // int32 or int64, detected on device
    const float* ea = (const float*)d_in[2];
    const float* W1_in  = (const float*)d_in[4];
    const float* b1_in  = (const float*)d_in[5];
    const float* W2_in  = (const float*)d_in[6];
    const float* W3_in  = (const float*)d_in[7];
    const float* b3_in  = (const float*)d_in[8];
    const float* W1_mid = (const float*)d_in[9];
    const float* b1_mid = (const float*)d_in[10];
    const float* W2_mid = (const float*)d_in[11];
    const float* W3_mid = (const float*)d_in[12];
    const float* b3_mid = (const float*)d_in[13];
    const float* W1_out = (const float*)d_in[14];
    const float* b1_out = (const float*)d_in[15];
    const float* W2_out = (const float*)d_in[16];
    const float* W3_out = (const float*)d_in[17];
    const float* b3_out = (const float*)d_in[18];

    float* out = (float*)d_out;

    float *d_h, *d_abc, *d_W0, *d_W1, *d_W2, *d_b0, *d_b1, *d_b2, *d_s;
    cudaGetSymbolAddress((void**)&d_h,   g_h);
    cudaGetSymbolAddress((void**)&d_abc, g_abc);
    cudaGetSymbolAddress((void**)&d_W0,  g_Wcat0);
    cudaGetSymbolAddress((void**)&d_W1,  g_Wcat1);
    cudaGetSymbolAddress((void**)&d_W2,  g_Wcat2);
    cudaGetSymbolAddress((void**)&d_b0,  g_bcat0);
    cudaGetSymbolAddress((void**)&d_b1,  g_bcat1);
    cudaGetSymbolAddress((void**)&d_b2,  g_bcat2);
    cudaGetSymbolAddress((void**)&d_s,   g_s);

    cudaFuncSetAttribute(tgemm_kernel, cudaFuncAttributeMaxDynamicSharedMemorySize, TG_SMEM);

    // --- pack all weights up front ---
    pack_w_kernel<<<(F_IN * WID + 255) / 256, 256>>>(W1_in,  b1_in,  W2_in,  W3_in,  b3_in,  F_IN, WID,   d_W0, d_b0);
    pack_w_kernel<<<(WID * WID + 255) / 256, 256>>>(W1_mid, b1_mid, W2_mid, W3_mid, b3_mid, WID,  WID,   d_W1, d_b1);
    pack_w_kernel<<<(WID * F_OUT + 255) / 256, 256>>>(W1_out, b1_out, W2_out, W3_out, b3_out, WID, F_OUT, d_W2, d_b2);

    // --- preprocessing: zero+detect, s[i], CSR ---
    zero_kernel<<<(NN + 255) / 256, 256>>>((const int*)ei);
    hist_kernel<<<(EE + 255) / 256, 256>>>(ei, ea);
    scan1_kernel<<<SCAN_NB, SCAN_B>>>();
    scan2_kernel<<<1, 32>>>();
    scan3_kernel<<<SCAN_NB, SCAN_B>>>();
    scatter_kernel<<<(EE + 255) / 256, 256>>>(ei, ea);

    const int spmm_blocks = (NN + 7) / 8;
    const int grid_m = (NN + 127) / 128;

    // --- layer 0 (in): x -> g_h ---
    {
        dim3 grid(grid_m, (3 * WID + 127) / 128);
        tgemm_kernel<<<grid, 256, TG_SMEM>>>(x, d_W0, d_b0, d_s, NN, WID, d_abc);
        spmm128_kernel<<<spmm_blocks, 256>>>(d_abc, d_h, 0);
    }

    // --- layers 1,2 (mid): g_h -> g_h ---
    for (int l = 0; l < 2; l++) {
        dim3 grid(grid_m, (3 * WID + 127) / 128);
        tgemm_kernel<<<grid, 256, TG_SMEM>>>(d_h, d_W1, d_b1, d_s, NN, WID, d_abc);
        spmm128_kernel<<<spmm_blocks, 256>>>(d_abc, d_h, 0);
    }

    // --- layer 3 (out): g_h -> d_out (lrelu then sigmoid) ---
    {
        dim3 grid(grid_m, (3 * F_OUT + 127) / 128);
        tgemm_kernel<<<grid, 256, TG_SMEM>>>(d_h, d_W2, d_b2, d_s, NN, F_OUT, d_abc);
        spmm64_kernel<<<spmm_blocks, 256>>>(d_abc, out, 1);
    }
}